// round 3
// baseline (speedup 1.0000x reference)
#include <cuda_runtime.h>
#include <cuda_bf16.h>
#include <math.h>

// Problem constants (match reference)
#define NN     50000
#define EE     800000
#define EP     850000     // edges + self loops
#define F_IN   128
#define HID    32
#define HEADS  4
#define HH     128        // HEADS*HID
#define CC     40
#define NEG_SLOPE 0.2f

// ---------------- scratch (device globals; no allocation allowed) ----------------
__device__ int   g_src[EP];
__device__ int   g_dst[EP];
__device__ int   g_flag32;           // 1 if edge_index stored as int32

__device__ float g_h1[NN * HH];      // x @ W1            [N,128]
__device__ float g_as1[NN * HEADS];  // src att logits    [N,4]
__device__ float g_ad1[NN * HEADS];  // dst att logits    [N,4]
__device__ float g_ew1[EP * HEADS];  // exp -> alpha      [E',4]
__device__ float g_s1[NN * HEADS];   // softmax denom     [N,4]
__device__ float g_out1[NN * HH];    // GAT1 out / elu    [N,128]
__device__ float g_h2[NN * CC];      // x_gat @ W2        [N,40]
__device__ float g_as2[NN];
__device__ float g_ad2[NN];
__device__ float g_ew2[EP];
__device__ float g_s2[NN];
__device__ float g_out2[NN * CC];    // GAT2 out          [N,40]
__device__ float g_hg1[NN * HID];    // x @ gcnW1         [N,32]
__device__ float g_norm[NN];         // deg -> rsqrt(deg)
__device__ float g_go1[NN * HID];    // GCN1 out          [N,32]
__device__ float g_hg2[NN * CC];     // relu(go1) @ gcnW2 [N,40]
__device__ float g_go2[NN * CC];     // GCN2 out          [N,40]

// Device-side symbol table. NEVER pass __device__ symbols from host code:
// on GB300 (ATS) the host shadow address is dereferenceable and writes go to
// host memory silently. All global-pointer resolution happens in device code.
#define PTR_H1   0
#define PTR_HG1  1
#define PTR_H2   2
#define PTR_HG2  3
#define PTR_OUT1 4
#define PTR_GO1  5
__device__ __forceinline__ float* g_ptr(int id) {
    switch (id) {
        case PTR_H1:   return g_h1;
        case PTR_HG1:  return g_hg1;
        case PTR_H2:   return g_h2;
        case PTR_HG2:  return g_hg2;
        case PTR_OUT1: return g_out1;
        case PTR_GO1:  return g_go1;
    }
    return 0;
}

// ---------------- zero accumulators + flag ----------------
__global__ void zero_all() {
    int i = blockIdx.x * blockDim.x + threadIdx.x;
    int stride = gridDim.x * blockDim.x;
    if (i == 0) g_flag32 = 0;
    for (int k = i; k < NN * HH; k += stride) g_out1[k] = 0.f;
    for (int k = i; k < NN * CC; k += stride) { g_out2[k] = 0.f; g_go2[k] = 0.f; }
    for (int k = i; k < NN * HID; k += stride) g_go1[k] = 0.f;
    for (int k = i; k < NN * HEADS; k += stride) g_s1[k] = 0.f;
    for (int k = i; k < NN; k += stride) { g_s2[k] = 0.f; g_norm[k] = 0.f; }
}

// ---------------- dtype detect: int64 => every odd 32-bit word is 0 ----------------
__global__ void detect_idx(const unsigned int* __restrict__ raw) {
    int i = blockIdx.x * blockDim.x + threadIdx.x;   // 65536 samples
    unsigned v = raw[2 * i + 1];
    if (v != 0u) g_flag32 = 1;   // benign race; any writer writes 1
}

// ---------------- convert to canonical int src/dst with virtual self loops ------
__global__ void convert_idx(const void* __restrict__ eidx) {
    int e = blockIdx.x * blockDim.x + threadIdx.x;
    if (e >= EP) return;
    int s, d;
    if (e < EE) {
        if (g_flag32) {
            s = ((const int*)eidx)[e];
            d = ((const int*)eidx)[EE + e];
        } else {
            s = (int)((const long long*)eidx)[e];
            d = (int)((const long long*)eidx)[EE + e];
        }
    } else {
        s = d = e - EE;
    }
    // Clamp defensively (avoids wild atomics if layout assumption is ever wrong)
    s = min(max(s, 0), NN - 1);
    d = min(max(d, 0), NN - 1);
    g_src[e] = s;
    g_dst[e] = d;
}

// ---------------- tiled SGEMM: C[M,N] = A[M,K] @ B[K,N] ----------------
// A: external pointer if aid<0, else device-global via tag.  C always via tag.
__global__ void sgemm(const float* __restrict__ Aext, int aid,
                      const float* __restrict__ B, int cid,
                      int M, int Nn, int K) {
    const float* A = (aid < 0) ? Aext : g_ptr(aid);
    float* Cm = g_ptr(cid);
    __shared__ float As[16][16];
    __shared__ float Bs[16][17];
    int tx = threadIdx.x, ty = threadIdx.y;
    int row = blockIdx.y * 16 + ty;
    int col = blockIdx.x * 16 + tx;
    float acc = 0.f;
    for (int k0 = 0; k0 < K; k0 += 16) {
        As[ty][tx] = (row < M && (k0 + tx) < K) ? A[row * K + k0 + tx] : 0.f;
        Bs[ty][tx] = ((k0 + ty) < K && col < Nn) ? B[(k0 + ty) * Nn + col] : 0.f;
        __syncthreads();
#pragma unroll
        for (int k = 0; k < 16; k++) acc += As[ty][k] * Bs[k][tx];
        __syncthreads();
    }
    if (row < M && col < Nn) Cm[row * Nn + col] = acc;
}

// ---------------- attention logits ----------------
__global__ void att_logits1(const float* __restrict__ att_src,
                            const float* __restrict__ att_dst) {
    int t = blockIdx.x * blockDim.x + threadIdx.x;
    if (t >= NN * HEADS) return;
    int n = t >> 2, h = t & 3;
    const float* hp = &g_h1[n * HH + h * HID];
    const float* as = &att_src[h * HID];
    const float* ad = &att_dst[h * HID];
    float s = 0.f, d = 0.f;
#pragma unroll
    for (int k = 0; k < HID; k++) { float v = hp[k]; s += v * as[k]; d += v * ad[k]; }
    g_as1[t] = s;
    g_ad1[t] = d;
}

__global__ void att_logits2(const float* __restrict__ att_src,
                            const float* __restrict__ att_dst) {
    int n = blockIdx.x * blockDim.x + threadIdx.x;
    if (n >= NN) return;
    const float* hp = &g_h2[n * CC];
    float s = 0.f, d = 0.f;
#pragma unroll
    for (int k = 0; k < CC; k++) { float v = hp[k]; s += v * att_src[k]; d += v * att_dst[k]; }
    g_as2[n] = s;
    g_ad2[n] = d;
}

// ---------------- GAT1 edge softmax weights (unnormalized) ----------------
__global__ void gat1_edge() {
    int e = blockIdx.x * blockDim.x + threadIdx.x;
    if (e >= EP) return;
    int src = g_src[e], dst = g_dst[e];
    float4 a = *(const float4*)&g_as1[src * 4];
    float4 b = *(const float4*)&g_ad1[dst * 4];
    float v[4] = { a.x + b.x, a.y + b.y, a.z + b.z, a.w + b.w };
#pragma unroll
    for (int h = 0; h < 4; h++) {
        float t = v[h];
        t = (t > 0.f) ? t : NEG_SLOPE * t;
        float w = __expf(t);            // logits O(1); softmax shift-invariant
        g_ew1[e * 4 + h] = w;
        atomicAdd(&g_s1[dst * 4 + h], w);
    }
}

// normalize: alpha = ew / s[dst]
__global__ void gat1_alpha() {
    int e = blockIdx.x * blockDim.x + threadIdx.x;
    if (e >= EP) return;
    int dst = g_dst[e];
    float4 w = *(const float4*)&g_ew1[e * 4];
    float4 s = *(const float4*)&g_s1[dst * 4];
    w.x /= s.x; w.y /= s.y; w.z /= s.z; w.w /= s.w;
    *(float4*)&g_ew1[e * 4] = w;
}

// ---------------- GAT1 aggregation: one thread per (edge, feature) ----------------
__global__ void gat1_agg() {
    long long t = (long long)blockIdx.x * blockDim.x + threadIdx.x;
    if (t >= (long long)EP * HH) return;
    int e = (int)(t >> 7);
    int f = (int)(t & 127);
    int h = f >> 5;
    int src = g_src[e], dst = g_dst[e];
    float alpha = g_ew1[e * 4 + h];
    atomicAdd(&g_out1[dst * HH + f], g_h1[src * HH + f] * alpha);
}

// ---------------- ELU ----------------
__global__ void elu_kernel(const float* __restrict__ bias) {
    int t = blockIdx.x * blockDim.x + threadIdx.x;
    if (t >= NN * HH) return;
    float v = g_out1[t] + bias[t & 127];
    g_out1[t] = (v > 0.f) ? v : expm1f(v);
}

// ---------------- GAT2 edge softmax ----------------
__global__ void gat2_edge() {
    int e = blockIdx.x * blockDim.x + threadIdx.x;
    if (e >= EP) return;
    int src = g_src[e], dst = g_dst[e];
    float t = g_as2[src] + g_ad2[dst];
    t = (t > 0.f) ? t : NEG_SLOPE * t;
    float w = __expf(t);
    g_ew2[e] = w;
    atomicAdd(&g_s2[dst], w);
}

__global__ void gat2_alpha() {
    int e = blockIdx.x * blockDim.x + threadIdx.x;
    if (e >= EP) return;
    g_ew2[e] /= g_s2[g_dst[e]];
}

// ---------------- GAT2 aggregation ----------------
__global__ void gat2_agg() {
    long long t = (long long)blockIdx.x * blockDim.x + threadIdx.x;
    if (t >= (long long)EP * CC) return;
    int e = (int)(t / CC);
    int c = (int)(t % CC);
    int src = g_src[e], dst = g_dst[e];
    float alpha = g_ew2[e];
    atomicAdd(&g_out2[dst * CC + c], g_h2[src * CC + c] * alpha);
}

// ---------------- GCN degree + norm ----------------
__global__ void gcn_deg() {
    int e = blockIdx.x * blockDim.x + threadIdx.x;
    if (e >= EP) return;
    atomicAdd(&g_norm[g_dst[e]], 1.0f);
}
__global__ void gcn_norm() {
    int n = blockIdx.x * blockDim.x + threadIdx.x;
    if (n >= NN) return;
    g_norm[n] = rsqrtf(g_norm[n]);
}

// ---------------- GCN1 aggregation ----------------
__global__ void gcn1_agg() {
    long long t = (long long)blockIdx.x * blockDim.x + threadIdx.x;
    if (t >= (long long)EP * HID) return;
    int e = (int)(t >> 5);
    int c = (int)(t & 31);
    int src = g_src[e], dst = g_dst[e];
    float coef = g_norm[src] * g_norm[dst];
    atomicAdd(&g_go1[dst * HID + c], g_hg1[src * HID + c] * coef);
}

__global__ void relu_go1(const float* __restrict__ bias) {
    int t = blockIdx.x * blockDim.x + threadIdx.x;
    if (t >= NN * HID) return;
    float v = g_go1[t] + bias[t & 31];
    g_go1[t] = (v > 0.f) ? v : 0.f;
}

// ---------------- GCN2 aggregation ----------------
__global__ void gcn2_agg() {
    long long t = (long long)blockIdx.x * blockDim.x + threadIdx.x;
    if (t >= (long long)EP * CC) return;
    int e = (int)(t / CC);
    int c = (int)(t % CC);
    int src = g_src[e], dst = g_dst[e];
    float coef = g_norm[src] * g_norm[dst];
    atomicAdd(&g_go2[dst * CC + c], g_hg2[src * CC + c] * coef);
}

// ---------------- final head ----------------
__global__ void final_head(const float* __restrict__ gat_b2,
                           const float* __restrict__ gcn_b2,
                           const float* __restrict__ lin_W,
                           const float* __restrict__ lin_b,
                           const float* __restrict__ wc_p,
                           const float* __restrict__ wt_p,
                           float* __restrict__ out) {
    int t = blockIdx.x * blockDim.x + threadIdx.x;
    if (t >= NN * CC) return;
    int n = t / CC, co = t % CC;
    float wc = *wc_p, wt = *wt_p;
    float acc = lin_b[co];
    const float* gcn = &g_go2[n * CC];
    const float* gat = &g_out2[n * CC];
#pragma unroll
    for (int j = 0; j < CC; j++)
        acc += (gcn[j] + gcn_b2[j]) * wc * lin_W[j * CC + co];
#pragma unroll
    for (int j = 0; j < CC; j++)
        acc += (gat[j] + gat_b2[j]) * wt * lin_W[(CC + j) * CC + co];
    out[t] = acc;
}

// ---------------- launch ----------------
extern "C" void kernel_launch(void* const* d_in, const int* in_sizes, int n_in,
                              void* d_out, int out_size) {
    const float* x      = (const float*)d_in[0];
    const void*  eidx   = d_in[1];
    const float* gat_W1 = (const float*)d_in[2];
    const float* att_s1 = (const float*)d_in[3];
    const float* att_d1 = (const float*)d_in[4];
    const float* gat_b1 = (const float*)d_in[5];
    const float* gat_W2 = (const float*)d_in[6];
    const float* att_s2 = (const float*)d_in[7];
    const float* att_d2 = (const float*)d_in[8];
    const float* gat_b2 = (const float*)d_in[9];
    const float* gcn_W1 = (const float*)d_in[10];
    const float* gcn_b1 = (const float*)d_in[11];
    const float* gcn_W2 = (const float*)d_in[12];
    const float* gcn_b2 = (const float*)d_in[13];
    const float* lin_W  = (const float*)d_in[14];
    const float* lin_b  = (const float*)d_in[15];
    const float* wc     = (const float*)d_in[16];
    const float* wt     = (const float*)d_in[17];
    float*       out    = (float*)d_out;

    zero_all<<<4096, 256>>>();

    detect_idx<<<256, 256>>>((const unsigned int*)eidx);
    convert_idx<<<(EP + 255) / 256, 256>>>(eidx);

    // Dense projections (A external, C via device-side tag)
    {
        dim3 b(16, 16);
        sgemm<<<dim3((HH + 15) / 16, (NN + 15) / 16), b>>>(x, -1, gat_W1, PTR_H1, NN, HH, F_IN);
        sgemm<<<dim3((HID + 15) / 16, (NN + 15) / 16), b>>>(x, -1, gcn_W1, PTR_HG1, NN, HID, F_IN);
    }

    // GAT layer 1
    att_logits1<<<(NN * HEADS + 255) / 256, 256>>>(att_s1, att_d1);
    gat1_edge<<<(EP + 255) / 256, 256>>>();
    gat1_alpha<<<(EP + 255) / 256, 256>>>();
    {
        long long tot = (long long)EP * HH;
        gat1_agg<<<(unsigned)((tot + 255) / 256), 256>>>();
    }
    elu_kernel<<<(NN * HH + 255) / 256, 256>>>(gat_b1);

    // GAT layer 2
    {
        dim3 b(16, 16);
        sgemm<<<dim3((CC + 15) / 16, (NN + 15) / 16), b>>>((const float*)0, PTR_OUT1, gat_W2, PTR_H2, NN, CC, HH);
    }
    att_logits2<<<(NN + 255) / 256, 256>>>(att_s2, att_d2);
    gat2_edge<<<(EP + 255) / 256, 256>>>();
    gat2_alpha<<<(EP + 255) / 256, 256>>>();
    {
        long long tot = (long long)EP * CC;
        gat2_agg<<<(unsigned)((tot + 255) / 256), 256>>>();
    }

    // GCN branch
    gcn_deg<<<(EP + 255) / 256, 256>>>();
    gcn_norm<<<(NN + 255) / 256, 256>>>();
    {
        long long tot = (long long)EP * HID;
        gcn1_agg<<<(unsigned)((tot + 255) / 256), 256>>>();
    }
    relu_go1<<<(NN * HID + 255) / 256, 256>>>(gcn_b1);
    {
        dim3 b(16, 16);
        sgemm<<<dim3((CC + 15) / 16, (NN + 15) / 16), b>>>((const float*)0, PTR_GO1, gcn_W2, PTR_HG2, NN, CC, HID);
    }
    {
        long long tot = (long long)EP * CC;
        gcn2_agg<<<(unsigned)((tot + 255) / 256), 256>>>();
    }

    // Final linear head
    final_head<<<(NN * CC + 255) / 256, 256>>>(gat_b2, gcn_b2, lin_W, lin_b, wc, wt, out);
}

// round 4
// speedup vs baseline: 2.0052x; 2.0052x over previous
#include <cuda_runtime.h>
#include <cuda_bf16.h>
#include <math.h>

// Problem constants (match reference)
#define NN     50000
#define EE     800000
#define EP     850000     // edges + self loops
#define F_IN   128
#define HID    32
#define HEADS  4
#define HH     128        // HEADS*HID
#define CC     40
#define NEG_SLOPE 0.2f

// ---------------- scratch (device globals; no allocation allowed) ----------------
__device__ int   g_src[EP];
__device__ int   g_dst[EP];
__device__ int   g_flag32;

__device__ int   g_deg[NN];
__device__ int   g_off[NN + 1];
__device__ int   g_cursor[NN];
__device__ int   g_csr_src[EP];      // src node per CSR slot (sorted by dst)

__device__ float g_h1[NN * HH];      // x @ W1            [N,128]
__device__ float g_as1[NN * HEADS];
__device__ float g_ad1[NN * HEADS];
__device__ float g_out1[NN * HH];    // GAT1 out (elu'd)  [N,128]
__device__ float g_h2[NN * CC];      // out1 @ W2         [N,40]
__device__ float g_as2[NN];
__device__ float g_ad2[NN];
__device__ float g_out2[NN * CC];    // GAT2 out          [N,40]
__device__ float g_hg1[NN * HID];    // x @ gcnW1         [N,32]
__device__ float g_norm[NN];         // rsqrt(deg)
__device__ float g_go1[NN * HID];    // GCN1 out (relu'd) [N,32]
__device__ float g_hg2[NN * CC];     // go1 @ gcnW2       [N,40]
__device__ float g_go2[NN * CC];     // GCN2 out          [N,40]

// Device-side symbol table: never pass __device__ symbols from host (ATS trap).
#define PTR_H1   0
#define PTR_HG1  1
#define PTR_H2   2
#define PTR_HG2  3
#define PTR_OUT1 4
#define PTR_GO1  5
__device__ __forceinline__ float* g_ptr(int id) {
    switch (id) {
        case PTR_H1:   return g_h1;
        case PTR_HG1:  return g_hg1;
        case PTR_H2:   return g_h2;
        case PTR_HG2:  return g_hg2;
        case PTR_OUT1: return g_out1;
        case PTR_GO1:  return g_go1;
    }
    return 0;
}

// ---------------- init: clear degree + flag ----------------
__global__ void zero_init() {
    int i = blockIdx.x * blockDim.x + threadIdx.x;
    if (i == 0) g_flag32 = 0;
    if (i < NN) g_deg[i] = 0;
}

// ---------------- dtype detect: int64 => every odd 32-bit word is 0 ----------------
__global__ void detect_idx(const unsigned int* __restrict__ raw) {
    int i = blockIdx.x * blockDim.x + threadIdx.x;   // 65536 samples
    unsigned v = raw[2 * i + 1];
    if (v != 0u) g_flag32 = 1;
}

// ---------------- convert edges, count degrees ----------------
__global__ void convert_idx(const void* __restrict__ eidx) {
    int e = blockIdx.x * blockDim.x + threadIdx.x;
    if (e >= EP) return;
    int s, d;
    if (e < EE) {
        if (g_flag32) {
            s = ((const int*)eidx)[e];
            d = ((const int*)eidx)[EE + e];
        } else {
            s = (int)((const long long*)eidx)[e];
            d = (int)((const long long*)eidx)[EE + e];
        }
    } else {
        s = d = e - EE;
    }
    s = min(max(s, 0), NN - 1);
    d = min(max(d, 0), NN - 1);
    g_src[e] = s;
    g_dst[e] = d;
    atomicAdd(&g_deg[d], 1);
}

// ---------------- single-block exclusive scan over degrees ----------------
__global__ void scan_offsets() {
    __shared__ int sh[1024];
    __shared__ int carry;
    if (threadIdx.x == 0) carry = 0;
    __syncthreads();
    for (int base = 0; base < NN; base += 1024) {
        int i = base + threadIdx.x;
        int v = (i < NN) ? g_deg[i] : 0;
        sh[threadIdx.x] = v;
        __syncthreads();
        for (int s = 1; s < 1024; s <<= 1) {
            int t = (threadIdx.x >= s) ? sh[threadIdx.x - s] : 0;
            __syncthreads();
            sh[threadIdx.x] += t;
            __syncthreads();
        }
        int c = carry;
        if (i < NN) {
            int excl = c + sh[threadIdx.x] - v;
            g_off[i] = excl;
            g_cursor[i] = excl;
        }
        int total = sh[1023];
        __syncthreads();
        if (threadIdx.x == 0) carry = c + total;
        __syncthreads();
    }
    if (threadIdx.x == 0) g_off[NN] = EP;
}

// ---------------- scatter edges into CSR slots ----------------
__global__ void scatter_csr() {
    int e = blockIdx.x * blockDim.x + threadIdx.x;
    if (e >= EP) return;
    int d = g_dst[e];
    int pos = atomicAdd(&g_cursor[d], 1);
    g_csr_src[pos] = g_src[e];
}

// ---------------- GCN norm from CSR degree ----------------
__global__ void gcn_norm() {
    int n = blockIdx.x * blockDim.x + threadIdx.x;
    if (n >= NN) return;
    g_norm[n] = rsqrtf((float)(g_off[n + 1] - g_off[n]));
}

// ---------------- register-blocked SGEMM: C[M,N] = A[M,K] @ B[K,N] ----------------
#define BM 64
#define BN 64
#define BK 16
__global__ void sgemm_rb(const float* __restrict__ Aext, int aid,
                         const float* __restrict__ B, int cid,
                         int M, int Nn, int K) {
    const float* A = (aid < 0) ? Aext : g_ptr(aid);
    float* Cm = g_ptr(cid);
    __shared__ float As[BK][BM + 1];
    __shared__ float Bs[BK][BN];
    int tid = threadIdx.x;
    int tx = tid % 16, ty = tid / 16;
    int row0 = blockIdx.y * BM, col0 = blockIdx.x * BN;
    float acc[4][4] = {};
    for (int k0 = 0; k0 < K; k0 += BK) {
        for (int i = tid; i < BM * BK; i += 256) {
            int r = i / BK, c = i % BK;
            int gr = row0 + r, gc = k0 + c;
            As[c][r] = (gr < M && gc < K) ? A[gr * K + gc] : 0.f;
        }
        for (int i = tid; i < BK * BN; i += 256) {
            int r = i / BN, c = i % BN;
            int gr = k0 + r, gc = col0 + c;
            Bs[r][c] = (gr < K && gc < Nn) ? B[gr * Nn + gc] : 0.f;
        }
        __syncthreads();
#pragma unroll
        for (int k = 0; k < BK; k++) {
            float a[4], b[4];
#pragma unroll
            for (int i = 0; i < 4; i++) a[i] = As[k][ty * 4 + i];
#pragma unroll
            for (int j = 0; j < 4; j++) b[j] = Bs[k][tx * 4 + j];
#pragma unroll
            for (int i = 0; i < 4; i++)
#pragma unroll
                for (int j = 0; j < 4; j++) acc[i][j] += a[i] * b[j];
        }
        __syncthreads();
    }
#pragma unroll
    for (int i = 0; i < 4; i++) {
        int gr = row0 + ty * 4 + i;
        if (gr >= M) continue;
#pragma unroll
        for (int j = 0; j < 4; j++) {
            int gc = col0 + tx * 4 + j;
            if (gc < Nn) Cm[gr * Nn + gc] = acc[i][j];
        }
    }
}

// ---------------- attention logits ----------------
__global__ void att_logits1(const float* __restrict__ att_src,
                            const float* __restrict__ att_dst) {
    int t = blockIdx.x * blockDim.x + threadIdx.x;
    if (t >= NN * HEADS) return;
    int n = t >> 2, h = t & 3;
    const float* hp = &g_h1[n * HH + h * HID];
    const float* as = &att_src[h * HID];
    const float* ad = &att_dst[h * HID];
    float s = 0.f, d = 0.f;
#pragma unroll
    for (int k = 0; k < HID; k++) { float v = hp[k]; s += v * as[k]; d += v * ad[k]; }
    g_as1[t] = s;
    g_ad1[t] = d;
}

__global__ void att_logits2(const float* __restrict__ att_src,
                            const float* __restrict__ att_dst) {
    int n = blockIdx.x * blockDim.x + threadIdx.x;
    if (n >= NN) return;
    const float* hp = &g_h2[n * CC];
    float s = 0.f, d = 0.f;
#pragma unroll
    for (int k = 0; k < CC; k++) { float v = hp[k]; s += v * att_src[k]; d += v * att_dst[k]; }
    g_as2[n] = s;
    g_ad2[n] = d;
}

// ---------------- GAT1 fused softmax + aggregation + bias + ELU ----------------
// One warp per dst node; lane owns features [lane*4, lane*4+4); head = lane>>3.
__global__ void gat1_agg_csr(const float* __restrict__ bias) {
    int warp = (blockIdx.x * blockDim.x + threadIdx.x) >> 5;
    if (warp >= NN) return;
    int lane = threadIdx.x & 31;
    int n = warp;
    int beg = g_off[n], end = g_off[n + 1];
    int h = lane >> 3;
    float ad = g_ad1[n * 4 + h];
    float4 acc = {0.f, 0.f, 0.f, 0.f};
    float sumw = 0.f;
    int src = (beg < end) ? g_csr_src[beg] : 0;
    for (int p = beg; p < end; p++) {
        int nsrc = (p + 1 < end) ? g_csr_src[p + 1] : 0;   // prefetch next src
        float t = g_as1[src * 4 + h] + ad;
        t = (t > 0.f) ? t : NEG_SLOPE * t;
        float w = __expf(t);                 // logits O(1); softmax shift-invariant
        sumw += w;
        float4 hv = *(const float4*)&g_h1[src * HH + lane * 4];
        acc.x += w * hv.x; acc.y += w * hv.y; acc.z += w * hv.z; acc.w += w * hv.w;
        src = nsrc;
    }
    float inv = 1.f / sumw;
    float4 bv = *(const float4*)&bias[lane * 4];
    float4 o;
    float vx = acc.x * inv + bv.x; o.x = (vx > 0.f) ? vx : expm1f(vx);
    float vy = acc.y * inv + bv.y; o.y = (vy > 0.f) ? vy : expm1f(vy);
    float vz = acc.z * inv + bv.z; o.z = (vz > 0.f) ? vz : expm1f(vz);
    float vw = acc.w * inv + bv.w; o.w = (vw > 0.f) ? vw : expm1f(vw);
    *(float4*)&g_out1[n * HH + lane * 4] = o;
}

// ---------------- GAT2 fused softmax + aggregation (bias added in final head) ----
__global__ void gat2_agg_csr() {
    int warp = (blockIdx.x * blockDim.x + threadIdx.x) >> 5;
    if (warp >= NN) return;
    int lane = threadIdx.x & 31;
    int n = warp;
    int beg = g_off[n], end = g_off[n + 1];
    float ad = g_ad2[n];
    float acc1 = 0.f, acc2 = 0.f, sumw = 0.f;
    int src = (beg < end) ? g_csr_src[beg] : 0;
    for (int p = beg; p < end; p++) {
        int nsrc = (p + 1 < end) ? g_csr_src[p + 1] : 0;
        float t = g_as2[src] + ad;
        t = (t > 0.f) ? t : NEG_SLOPE * t;
        float w = __expf(t);
        sumw += w;
        acc1 += w * g_h2[src * CC + lane];
        if (lane < CC - 32) acc2 += w * g_h2[src * CC + 32 + lane];
        src = nsrc;
    }
    float inv = 1.f / sumw;
    g_out2[n * CC + lane] = acc1 * inv;
    if (lane < CC - 32) g_out2[n * CC + 32 + lane] = acc2 * inv;
}

// ---------------- GCN1 fused aggregation + bias + ReLU ----------------
__global__ void gcn1_agg_csr(const float* __restrict__ bias) {
    int warp = (blockIdx.x * blockDim.x + threadIdx.x) >> 5;
    if (warp >= NN) return;
    int lane = threadIdx.x & 31;
    int n = warp;
    int beg = g_off[n], end = g_off[n + 1];
    float nd = g_norm[n];
    float acc = 0.f;
    int src = (beg < end) ? g_csr_src[beg] : 0;
    for (int p = beg; p < end; p++) {
        int nsrc = (p + 1 < end) ? g_csr_src[p + 1] : 0;
        float coef = g_norm[src] * nd;
        acc += coef * g_hg1[src * HID + lane];
        src = nsrc;
    }
    float v = acc + bias[lane];
    g_go1[n * HID + lane] = (v > 0.f) ? v : 0.f;
}

// ---------------- GCN2 aggregation (bias added in final head) ----------------
__global__ void gcn2_agg_csr() {
    int warp = (blockIdx.x * blockDim.x + threadIdx.x) >> 5;
    if (warp >= NN) return;
    int lane = threadIdx.x & 31;
    int n = warp;
    int beg = g_off[n], end = g_off[n + 1];
    float nd = g_norm[n];
    float acc1 = 0.f, acc2 = 0.f;
    int src = (beg < end) ? g_csr_src[beg] : 0;
    for (int p = beg; p < end; p++) {
        int nsrc = (p + 1 < end) ? g_csr_src[p + 1] : 0;
        float coef = g_norm[src] * nd;
        acc1 += coef * g_hg2[src * CC + lane];
        if (lane < CC - 32) acc2 += coef * g_hg2[src * CC + 32 + lane];
        src = nsrc;
    }
    g_go2[n * CC + lane] = acc1;
    if (lane < CC - 32) g_go2[n * CC + 32 + lane] = acc2;
}

// ---------------- final head ----------------
__global__ void final_head(const float* __restrict__ gat_b2,
                           const float* __restrict__ gcn_b2,
                           const float* __restrict__ lin_W,
                           const float* __restrict__ lin_b,
                           const float* __restrict__ wc_p,
                           const float* __restrict__ wt_p,
                           float* __restrict__ out) {
    int t = blockIdx.x * blockDim.x + threadIdx.x;
    if (t >= NN * CC) return;
    int n = t / CC, co = t % CC;
    float wc = *wc_p, wt = *wt_p;
    float acc = lin_b[co];
    const float* gcn = &g_go2[n * CC];
    const float* gat = &g_out2[n * CC];
#pragma unroll
    for (int j = 0; j < CC; j++)
        acc += (gcn[j] + gcn_b2[j]) * wc * lin_W[j * CC + co];
#pragma unroll
    for (int j = 0; j < CC; j++)
        acc += (gat[j] + gat_b2[j]) * wt * lin_W[(CC + j) * CC + co];
    out[t] = acc;
}

// ---------------- launch ----------------
extern "C" void kernel_launch(void* const* d_in, const int* in_sizes, int n_in,
                              void* d_out, int out_size) {
    const float* x      = (const float*)d_in[0];
    const void*  eidx   = d_in[1];
    const float* gat_W1 = (const float*)d_in[2];
    const float* att_s1 = (const float*)d_in[3];
    const float* att_d1 = (const float*)d_in[4];
    const float* gat_b1 = (const float*)d_in[5];
    const float* gat_W2 = (const float*)d_in[6];
    const float* att_s2 = (const float*)d_in[7];
    const float* att_d2 = (const float*)d_in[8];
    const float* gat_b2 = (const float*)d_in[9];
    const float* gcn_W1 = (const float*)d_in[10];
    const float* gcn_b1 = (const float*)d_in[11];
    const float* gcn_W2 = (const float*)d_in[12];
    const float* gcn_b2 = (const float*)d_in[13];
    const float* lin_W  = (const float*)d_in[14];
    const float* lin_b  = (const float*)d_in[15];
    const float* wc     = (const float*)d_in[16];
    const float* wt     = (const float*)d_in[17];
    float*       out    = (float*)d_out;

    const int WPB = 8;                 // warps per block in agg kernels
    const int AGG_BLK = (NN + WPB - 1) / WPB;

    zero_init<<<(NN + 255) / 256, 256>>>();
    detect_idx<<<256, 256>>>((const unsigned int*)eidx);
    convert_idx<<<(EP + 255) / 256, 256>>>(eidx);
    scan_offsets<<<1, 1024>>>();
    scatter_csr<<<(EP + 255) / 256, 256>>>();
    gcn_norm<<<(NN + 255) / 256, 256>>>();

    // Dense projections
    sgemm_rb<<<dim3((HH + BN - 1) / BN, (NN + BM - 1) / BM), 256>>>(x, -1, gat_W1, PTR_H1, NN, HH, F_IN);
    sgemm_rb<<<dim3((HID + BN - 1) / BN, (NN + BM - 1) / BM), 256>>>(x, -1, gcn_W1, PTR_HG1, NN, HID, F_IN);

    // GAT layer 1 (fused)
    att_logits1<<<(NN * HEADS + 255) / 256, 256>>>(att_s1, att_d1);
    gat1_agg_csr<<<AGG_BLK, WPB * 32>>>(gat_b1);

    // GAT layer 2 (fused)
    sgemm_rb<<<dim3((CC + BN - 1) / BN, (NN + BM - 1) / BM), 256>>>((const float*)0, PTR_OUT1, gat_W2, PTR_H2, NN, CC, HH);
    att_logits2<<<(NN + 255) / 256, 256>>>(att_s2, att_d2);
    gat2_agg_csr<<<AGG_BLK, WPB * 32>>>();

    // GCN branch (fused)
    gcn1_agg_csr<<<AGG_BLK, WPB * 32>>>(gcn_b1);
    sgemm_rb<<<dim3((CC + BN - 1) / BN, (NN + BM - 1) / BM), 256>>>((const float*)0, PTR_GO1, gcn_W2, PTR_HG2, NN, CC, HID);
    gcn2_agg_csr<<<AGG_BLK, WPB * 32>>>();

    // Final linear head
    final_head<<<(NN * CC + 255) / 256, 256>>>(gat_b2, gcn_b2, lin_W, lin_b, wc, wt, out);
}

// round 5
// speedup vs baseline: 2.3679x; 1.1809x over previous
#include <cuda_runtime.h>
#include <cuda_bf16.h>
#include <math.h>

// Problem constants (match reference)
#define NN     50000
#define EE     800000
#define EP     850000     // edges + self loops
#define F_IN   128
#define HID    32
#define HEADS  4
#define HH     128        // HEADS*HID
#define CC     40
#define NEG_SLOPE 0.2f

#define SCAN_CHUNK 1024
#define SCAN_BLOCKS ((NN + SCAN_CHUNK - 1) / SCAN_CHUNK)   // 49

// ---------------- scratch (device globals; no allocation allowed) ----------------
__device__ int   g_flag32;
__device__ int   g_deg[NN];
__device__ int   g_off[NN + 1];
__device__ int   g_cursor[NN];
__device__ int   g_bsum[SCAN_BLOCKS];
__device__ int   g_csr_src[EP];      // src node per CSR slot (grouped by dst)

__device__ float g_h1[NN * HH];      // x @ W1            [N,128]
__device__ float g_as1[NN * HEADS];
__device__ float g_ad1[NN * HEADS];
__device__ float g_out1[NN * HH];    // GAT1 out (elu'd)  [N,128]
__device__ float g_h2[NN * CC];      // out1 @ W2         [N,40]
__device__ float g_as2[NN];
__device__ float g_ad2[NN];
__device__ float g_out2[NN * CC];    // GAT2 out          [N,40]
__device__ float g_hg1[NN * HID];    // x @ gcnW1         [N,32]
__device__ float g_norm[NN];         // rsqrt(deg)
__device__ float g_go1[NN * HID];    // GCN1 out (relu'd) [N,32]
__device__ float g_hg2[NN * CC];     // go1 @ gcnW2       [N,40]
__device__ float g_go2[NN * CC];     // GCN2 out          [N,40]

// Device-side symbol table: never pass __device__ symbols from host (ATS trap).
#define PTR_H1   0
#define PTR_HG1  1
#define PTR_H2   2
#define PTR_HG2  3
#define PTR_OUT1 4
#define PTR_GO1  5
__device__ __forceinline__ float* g_ptr(int id) {
    switch (id) {
        case PTR_H1:   return g_h1;
        case PTR_HG1:  return g_hg1;
        case PTR_H2:   return g_h2;
        case PTR_HG2:  return g_hg2;
        case PTR_OUT1: return g_out1;
        case PTR_GO1:  return g_go1;
    }
    return 0;
}

// ---------------- init ----------------
__global__ void zero_init() {
    int i = blockIdx.x * blockDim.x + threadIdx.x;
    if (i == 0) g_flag32 = 0;
    if (i < NN) g_deg[i] = 0;
}

// ---------------- dtype detect: int64 => every odd 32-bit word is 0 ----------------
__global__ void detect_idx(const unsigned int* __restrict__ raw) {
    int i = blockIdx.x * blockDim.x + threadIdx.x;   // 65536 samples
    unsigned v = raw[2 * i + 1];
    if (v != 0u) g_flag32 = 1;
}

// ---------------- read dst helper ----------------
__device__ __forceinline__ int load_node(const void* eidx, long long idx) {
    int v = g_flag32 ? ((const int*)eidx)[idx]
                     : (int)((const long long*)eidx)[idx];
    return min(max(v, 0), NN - 1);
}

// ---------------- pass 1: count degrees (incl. self loops) ----------------
__global__ void count_deg(const void* __restrict__ eidx) {
    int e = blockIdx.x * blockDim.x + threadIdx.x;
    if (e >= EP) return;
    int d = (e < EE) ? load_node(eidx, (long long)EE + e) : (e - EE);
    atomicAdd(&g_deg[d], 1);
}

// ---------------- 3-phase scan ----------------
__global__ void scan_phase1() {
    __shared__ int warp_sums[32];
    int b = blockIdx.x;
    int i = b * SCAN_CHUNK + threadIdx.x;
    int lane = threadIdx.x & 31, wid = threadIdx.x >> 5;
    int v = (i < NN) ? g_deg[i] : 0;
    // warp inclusive scan
    int x = v;
#pragma unroll
    for (int s = 1; s < 32; s <<= 1) {
        int t = __shfl_up_sync(0xffffffff, x, s);
        if (lane >= s) x += t;
    }
    if (lane == 31) warp_sums[wid] = x;
    __syncthreads();
    if (wid == 0) {
        int ws = (lane < 32) ? warp_sums[lane] : 0;
#pragma unroll
        for (int s = 1; s < 32; s <<= 1) {
            int t = __shfl_up_sync(0xffffffff, ws, s);
            if (lane >= s) ws += t;
        }
        warp_sums[lane] = ws;
    }
    __syncthreads();
    int prefix = (wid > 0) ? warp_sums[wid - 1] : 0;
    int excl = prefix + x - v;     // exclusive within block
    if (i < NN) g_off[i] = excl;
    if (threadIdx.x == SCAN_CHUNK - 1) g_bsum[b] = prefix + x;
}

__global__ void scan_phase2() {
    // single warp scans SCAN_BLOCKS(<=49) block sums -> exclusive prefixes
    __shared__ int sh[64];
    int lane = threadIdx.x;
    int v0 = (lane < SCAN_BLOCKS) ? g_bsum[lane] : 0;
    int v1 = (lane + 32 < SCAN_BLOCKS) ? g_bsum[lane + 32] : 0;
    int x = v0;
#pragma unroll
    for (int s = 1; s < 32; s <<= 1) {
        int t = __shfl_up_sync(0xffffffff, x, s);
        if (lane >= s) x += t;
    }
    int tot0 = __shfl_sync(0xffffffff, x, 31);
    int y = v1;
#pragma unroll
    for (int s = 1; s < 32; s <<= 1) {
        int t = __shfl_up_sync(0xffffffff, y, s);
        if (lane >= s) y += t;
    }
    sh[lane] = x - v0;                 // exclusive
    sh[lane + 32] = tot0 + y - v1;
    __syncwarp();
    if (lane < SCAN_BLOCKS) g_bsum[lane] = sh[lane];
    if (lane + 32 < SCAN_BLOCKS) g_bsum[lane + 32] = sh[lane + 32];
}

__global__ void scan_phase3() {
    int i = blockIdx.x * blockDim.x + threadIdx.x;
    if (i == 0) g_off[NN] = EP;
    if (i >= NN) return;
    int o = g_off[i] + g_bsum[i / SCAN_CHUNK];
    g_off[i] = o;
    g_cursor[i] = o;
    // norm = rsqrt(deg)
    g_norm[i] = rsqrtf((float)g_deg[i]);
}

// ---------------- pass 2: scatter into CSR directly from edge_index ----------------
__global__ void scatter_csr(const void* __restrict__ eidx) {
    int e = blockIdx.x * blockDim.x + threadIdx.x;
    if (e >= EP) return;
    int s, d;
    if (e < EE) {
        s = load_node(eidx, e);
        d = load_node(eidx, (long long)EE + e);
    } else {
        s = d = e - EE;
    }
    int pos = atomicAdd(&g_cursor[d], 1);
    g_csr_src[pos] = s;
}

// ---------------- register-blocked SGEMM: C[M,N] = A[M,K] @ B[K,N] ----------------
#define BM 64
#define BN 64
#define BK 16
__global__ void sgemm_rb(const float* __restrict__ Aext, int aid,
                         const float* __restrict__ B, int cid,
                         int M, int Nn, int K) {
    const float* A = (aid < 0) ? Aext : g_ptr(aid);
    float* Cm = g_ptr(cid);
    __shared__ float As[BK][BM + 1];
    __shared__ float Bs[BK][BN];
    int tid = threadIdx.x;
    int tx = tid % 16, ty = tid / 16;
    int row0 = blockIdx.y * BM, col0 = blockIdx.x * BN;
    float acc[4][4] = {};
    for (int k0 = 0; k0 < K; k0 += BK) {
        for (int i = tid; i < BM * BK; i += 256) {
            int r = i / BK, c = i % BK;
            int gr = row0 + r, gc = k0 + c;
            As[c][r] = (gr < M && gc < K) ? A[gr * K + gc] : 0.f;
        }
        for (int i = tid; i < BK * BN; i += 256) {
            int r = i / BN, c = i % BN;
            int gr = k0 + r, gc = col0 + c;
            Bs[r][c] = (gr < K && gc < Nn) ? B[gr * Nn + gc] : 0.f;
        }
        __syncthreads();
#pragma unroll
        for (int k = 0; k < BK; k++) {
            float a[4], b[4];
#pragma unroll
            for (int i = 0; i < 4; i++) a[i] = As[k][ty * 4 + i];
#pragma unroll
            for (int j = 0; j < 4; j++) b[j] = Bs[k][tx * 4 + j];
#pragma unroll
            for (int i = 0; i < 4; i++)
#pragma unroll
                for (int j = 0; j < 4; j++) acc[i][j] += a[i] * b[j];
        }
        __syncthreads();
    }
#pragma unroll
    for (int i = 0; i < 4; i++) {
        int gr = row0 + ty * 4 + i;
        if (gr >= M) continue;
#pragma unroll
        for (int j = 0; j < 4; j++) {
            int gc = col0 + tx * 4 + j;
            if (gc < Nn) Cm[gr * Nn + gc] = acc[i][j];
        }
    }
}

// ---------------- attention logits ----------------
__global__ void att_logits1(const float* __restrict__ att_src,
                            const float* __restrict__ att_dst) {
    int t = blockIdx.x * blockDim.x + threadIdx.x;
    if (t >= NN * HEADS) return;
    int n = t >> 2, h = t & 3;
    const float* hp = &g_h1[n * HH + h * HID];
    const float* as = &att_src[h * HID];
    const float* ad = &att_dst[h * HID];
    float s = 0.f, d = 0.f;
#pragma unroll
    for (int k = 0; k < HID; k++) { float v = hp[k]; s += v * as[k]; d += v * ad[k]; }
    g_as1[t] = s;
    g_ad1[t] = d;
}

__global__ void att_logits2(const float* __restrict__ att_src,
                            const float* __restrict__ att_dst) {
    int n = blockIdx.x * blockDim.x + threadIdx.x;
    if (n >= NN) return;
    const float* hp = &g_h2[n * CC];
    float s = 0.f, d = 0.f;
#pragma unroll
    for (int k = 0; k < CC; k++) { float v = hp[k]; s += v * att_src[k]; d += v * att_dst[k]; }
    g_as2[n] = s;
    g_ad2[n] = d;
}

// ---------------- GAT1 fused softmax + aggregation + bias + ELU ----------------
// One warp per dst node; lane owns features [lane*4, lane*4+4); head = lane>>3.
// 2x edge unroll for MLP on the gather chain.
__global__ void gat1_agg_csr(const float* __restrict__ bias) {
    int warp = (blockIdx.x * blockDim.x + threadIdx.x) >> 5;
    if (warp >= NN) return;
    int lane = threadIdx.x & 31;
    int n = warp;
    int beg = g_off[n], end = g_off[n + 1];
    int h = lane >> 3;
    float ad = g_ad1[n * 4 + h];
    float4 acc = {0.f, 0.f, 0.f, 0.f};
    float sumw = 0.f;
    int p = beg;
    for (; p + 1 < end; p += 2) {
        int s0 = g_csr_src[p];
        int s1 = g_csr_src[p + 1];
        float l0 = g_as1[s0 * 4 + h] + ad;
        float l1 = g_as1[s1 * 4 + h] + ad;
        float4 h0 = *(const float4*)&g_h1[s0 * HH + lane * 4];
        float4 h1 = *(const float4*)&g_h1[s1 * HH + lane * 4];
        l0 = (l0 > 0.f) ? l0 : NEG_SLOPE * l0;
        l1 = (l1 > 0.f) ? l1 : NEG_SLOPE * l1;
        float w0 = __expf(l0);
        float w1 = __expf(l1);
        sumw += w0 + w1;
        acc.x += w0 * h0.x + w1 * h1.x;
        acc.y += w0 * h0.y + w1 * h1.y;
        acc.z += w0 * h0.z + w1 * h1.z;
        acc.w += w0 * h0.w + w1 * h1.w;
    }
    if (p < end) {
        int s0 = g_csr_src[p];
        float l0 = g_as1[s0 * 4 + h] + ad;
        float4 h0 = *(const float4*)&g_h1[s0 * HH + lane * 4];
        l0 = (l0 > 0.f) ? l0 : NEG_SLOPE * l0;
        float w0 = __expf(l0);
        sumw += w0;
        acc.x += w0 * h0.x; acc.y += w0 * h0.y; acc.z += w0 * h0.z; acc.w += w0 * h0.w;
    }
    float inv = 1.f / sumw;
    float4 bv = *(const float4*)&bias[lane * 4];
    float4 o;
    float vx = acc.x * inv + bv.x; o.x = (vx > 0.f) ? vx : expm1f(vx);
    float vy = acc.y * inv + bv.y; o.y = (vy > 0.f) ? vy : expm1f(vy);
    float vz = acc.z * inv + bv.z; o.z = (vz > 0.f) ? vz : expm1f(vz);
    float vw = acc.w * inv + bv.w; o.w = (vw > 0.f) ? vw : expm1f(vw);
    *(float4*)&g_out1[n * HH + lane * 4] = o;
}

// ---------------- GAT2 fused softmax + aggregation ----------------
__global__ void gat2_agg_csr() {
    int warp = (blockIdx.x * blockDim.x + threadIdx.x) >> 5;
    if (warp >= NN) return;
    int lane = threadIdx.x & 31;
    int n = warp;
    int beg = g_off[n], end = g_off[n + 1];
    float ad = g_ad2[n];
    float acc1 = 0.f, acc2 = 0.f, sumw = 0.f;
    int p = beg;
    for (; p + 1 < end; p += 2) {
        int s0 = g_csr_src[p];
        int s1 = g_csr_src[p + 1];
        float l0 = g_as2[s0] + ad;
        float l1 = g_as2[s1] + ad;
        float a0 = g_h2[s0 * CC + lane];
        float a1 = g_h2[s1 * CC + lane];
        float b0 = (lane < CC - 32) ? g_h2[s0 * CC + 32 + lane] : 0.f;
        float b1 = (lane < CC - 32) ? g_h2[s1 * CC + 32 + lane] : 0.f;
        l0 = (l0 > 0.f) ? l0 : NEG_SLOPE * l0;
        l1 = (l1 > 0.f) ? l1 : NEG_SLOPE * l1;
        float w0 = __expf(l0), w1 = __expf(l1);
        sumw += w0 + w1;
        acc1 += w0 * a0 + w1 * a1;
        acc2 += w0 * b0 + w1 * b1;
    }
    if (p < end) {
        int s0 = g_csr_src[p];
        float l0 = g_as2[s0] + ad;
        float a0 = g_h2[s0 * CC + lane];
        float b0 = (lane < CC - 32) ? g_h2[s0 * CC + 32 + lane] : 0.f;
        l0 = (l0 > 0.f) ? l0 : NEG_SLOPE * l0;
        float w0 = __expf(l0);
        sumw += w0;
        acc1 += w0 * a0;
        acc2 += w0 * b0;
    }
    float inv = 1.f / sumw;
    g_out2[n * CC + lane] = acc1 * inv;
    if (lane < CC - 32) g_out2[n * CC + 32 + lane] = acc2 * inv;
}

// ---------------- GCN1 fused aggregation + bias + ReLU ----------------
__global__ void gcn1_agg_csr(const float* __restrict__ bias) {
    int warp = (blockIdx.x * blockDim.x + threadIdx.x) >> 5;
    if (warp >= NN) return;
    int lane = threadIdx.x & 31;
    int n = warp;
    int beg = g_off[n], end = g_off[n + 1];
    float nd = g_norm[n];
    float acc = 0.f;
    int p = beg;
    for (; p + 1 < end; p += 2) {
        int s0 = g_csr_src[p];
        int s1 = g_csr_src[p + 1];
        float c0 = g_norm[s0];
        float c1 = g_norm[s1];
        float v0 = g_hg1[s0 * HID + lane];
        float v1 = g_hg1[s1 * HID + lane];
        acc += c0 * v0 + c1 * v1;
    }
    if (p < end) {
        int s0 = g_csr_src[p];
        acc += g_norm[s0] * g_hg1[s0 * HID + lane];
    }
    float v = acc * nd + bias[lane];
    g_go1[n * HID + lane] = (v > 0.f) ? v : 0.f;
}

// ---------------- GCN2 aggregation ----------------
__global__ void gcn2_agg_csr() {
    int warp = (blockIdx.x * blockDim.x + threadIdx.x) >> 5;
    if (warp >= NN) return;
    int lane = threadIdx.x & 31;
    int n = warp;
    int beg = g_off[n], end = g_off[n + 1];
    float nd = g_norm[n];
    float acc1 = 0.f, acc2 = 0.f;
    int p = beg;
    for (; p + 1 < end; p += 2) {
        int s0 = g_csr_src[p];
        int s1 = g_csr_src[p + 1];
        float c0 = g_norm[s0], c1 = g_norm[s1];
        float a0 = g_hg2[s0 * CC + lane];
        float a1 = g_hg2[s1 * CC + lane];
        float b0 = (lane < CC - 32) ? g_hg2[s0 * CC + 32 + lane] : 0.f;
        float b1 = (lane < CC - 32) ? g_hg2[s1 * CC + 32 + lane] : 0.f;
        acc1 += c0 * a0 + c1 * a1;
        acc2 += c0 * b0 + c1 * b1;
    }
    if (p < end) {
        int s0 = g_csr_src[p];
        float c0 = g_norm[s0];
        acc1 += c0 * g_hg2[s0 * CC + lane];
        if (lane < CC - 32) acc2 += c0 * g_hg2[s0 * CC + 32 + lane];
    }
    g_go2[n * CC + lane] = acc1 * nd;
    if (lane < CC - 32) g_go2[n * CC + 32 + lane] = acc2 * nd;
}

// ---------------- final head ----------------
__global__ void final_head(const float* __restrict__ gat_b2,
                           const float* __restrict__ gcn_b2,
                           const float* __restrict__ lin_W,
                           const float* __restrict__ lin_b,
                           const float* __restrict__ wc_p,
                           const float* __restrict__ wt_p,
                           float* __restrict__ out) {
    int t = blockIdx.x * blockDim.x + threadIdx.x;
    if (t >= NN * CC) return;
    int n = t / CC, co = t % CC;
    float wc = *wc_p, wt = *wt_p;
    float acc = lin_b[co];
    const float* gcn = &g_go2[n * CC];
    const float* gat = &g_out2[n * CC];
#pragma unroll
    for (int j = 0; j < CC; j++)
        acc += (gcn[j] + gcn_b2[j]) * wc * lin_W[j * CC + co];
#pragma unroll
    for (int j = 0; j < CC; j++)
        acc += (gat[j] + gat_b2[j]) * wt * lin_W[(CC + j) * CC + co];
    out[t] = acc;
}

// ---------------- launch ----------------
extern "C" void kernel_launch(void* const* d_in, const int* in_sizes, int n_in,
                              void* d_out, int out_size) {
    const float* x      = (const float*)d_in[0];
    const void*  eidx   = d_in[1];
    const float* gat_W1 = (const float*)d_in[2];
    const float* att_s1 = (const float*)d_in[3];
    const float* att_d1 = (const float*)d_in[4];
    const float* gat_b1 = (const float*)d_in[5];
    const float* gat_W2 = (const float*)d_in[6];
    const float* att_s2 = (const float*)d_in[7];
    const float* att_d2 = (const float*)d_in[8];
    const float* gat_b2 = (const float*)d_in[9];
    const float* gcn_W1 = (const float*)d_in[10];
    const float* gcn_b1 = (const float*)d_in[11];
    const float* gcn_W2 = (const float*)d_in[12];
    const float* gcn_b2 = (const float*)d_in[13];
    const float* lin_W  = (const float*)d_in[14];
    const float* lin_b  = (const float*)d_in[15];
    const float* wc     = (const float*)d_in[16];
    const float* wt     = (const float*)d_in[17];
    float*       out    = (float*)d_out;

    const int WPB = 8;
    const int AGG_BLK = (NN + WPB - 1) / WPB;

    zero_init<<<(NN + 255) / 256, 256>>>();
    detect_idx<<<256, 256>>>((const unsigned int*)eidx);
    count_deg<<<(EP + 255) / 256, 256>>>(eidx);
    scan_phase1<<<SCAN_BLOCKS, SCAN_CHUNK>>>();
    scan_phase2<<<1, 32>>>();
    scan_phase3<<<(NN + 255) / 256, 256>>>();
    scatter_csr<<<(EP + 255) / 256, 256>>>(eidx);

    // Dense projections
    sgemm_rb<<<dim3((HH + BN - 1) / BN, (NN + BM - 1) / BM), 256>>>(x, -1, gat_W1, PTR_H1, NN, HH, F_IN);
    sgemm_rb<<<dim3((HID + BN - 1) / BN, (NN + BM - 1) / BM), 256>>>(x, -1, gcn_W1, PTR_HG1, NN, HID, F_IN);

    // GAT layer 1 (fused)
    att_logits1<<<(NN * HEADS + 255) / 256, 256>>>(att_s1, att_d1);
    gat1_agg_csr<<<AGG_BLK, WPB * 32>>>(gat_b1);

    // GAT layer 2 (fused)
    sgemm_rb<<<dim3((CC + BN - 1) / BN, (NN + BM - 1) / BM), 256>>>((const float*)0, PTR_OUT1, gat_W2, PTR_H2, NN, CC, HH);
    att_logits2<<<(NN + 255) / 256, 256>>>(att_s2, att_d2);
    gat2_agg_csr<<<AGG_BLK, WPB * 32>>>();

    // GCN branch (fused)
    gcn1_agg_csr<<<AGG_BLK, WPB * 32>>>(gcn_b1);
    sgemm_rb<<<dim3((CC + BN - 1) / BN, (NN + BM - 1) / BM), 256>>>((const float*)0, PTR_GO1, gcn_W2, PTR_HG2, NN, CC, HID);
    gcn2_agg_csr<<<AGG_BLK, WPB * 32>>>();

    // Final linear head
    final_head<<<(NN * CC + 255) / 256, 256>>>(gat_b2, gcn_b2, lin_W, lin_b, wc, wt, out);
}